// round 11
// baseline (speedup 1.0000x reference)
#include <cuda_runtime.h>
#include <cuda_bf16.h>

#define BB 16384
#define SS 4
#define LL 16
#define DD 256
#define BOS_ID 98
#define D4 (DD / 4)              // 64 float4 per row

#define BPC 8                    // batch elems per block (1 per warp)
#define SLOTROWS (BPC * SS)      // 32 slot rows per block
#define OUTR (BPC * 5)           // 40 output rows per block
#define THREADS 256
#define BLOCKS (BB / BPC)        // 2048

__device__ __forceinline__ void acc4(float4& a0, float4& a1, float m,
                                     const float4 e0, const float4 e1)
{
    a0.x = fmaf(m, e0.x, a0.x); a0.y = fmaf(m, e0.y, a0.y);
    a0.z = fmaf(m, e0.z, a0.z); a0.w = fmaf(m, e0.w, a0.w);
    a1.x = fmaf(m, e1.x, a1.x); a1.y = fmaf(m, e1.y, a1.y);
    a1.z = fmaf(m, e1.z, a1.z); a1.w = fmaf(m, e1.w, a1.w);
}

__global__ void __launch_bounds__(THREADS) actions_emb_kernel(
    const int*    __restrict__ char_ids,     // (B, S, L)
    const int*    __restrict__ char_len,     // (B, S)
    const int*    __restrict__ action_ids,   // (B, S)
    const int*    __restrict__ slot_type,    // (B, S)
    const float4* __restrict__ char_table,   // (N_CHAR, 64)
    const float4* __restrict__ action_table, // (N_ACT, 64)
    float4*       __restrict__ out)          // (B, 5, 64)
{
    __shared__ __align__(16) float4 s_out[OUTR * D4];   // 40960 B
    __shared__ __align__(16) int    s_ids[SLOTROWS * LL]; // 2048 B
    __shared__ int s_st[SLOTROWS], s_len[SLOTROWS], s_ai[SLOTROWS];

    const int tid = threadIdx.x;

    // ---- Lane-parallel control staging: 7 LDG + 7 STS for 32 rows ----
    if (tid < 128) {
        ((int4*)s_ids)[tid] =
            __ldg(&((const int4*)char_ids)[blockIdx.x * 128 + tid]);
    } else if (tid < 160) {
        s_st[tid - 128]  = __ldg(&slot_type [blockIdx.x * SLOTROWS + tid - 128]);
    } else if (tid < 192) {
        s_len[tid - 160] = __ldg(&char_len  [blockIdx.x * SLOTROWS + tid - 160]);
    } else if (tid < 224) {
        s_ai[tid - 192]  = __ldg(&action_ids[blockIdx.x * SLOTROWS + tid - 192]);
    }
    __syncthreads();

    const int w    = tid >> 5;     // warp -> batch elem b_local
    const int lane = tid & 31;

    // ---- BOS row (L1-hot) ----
    {
        const float4 r0 = __ldg(&action_table[BOS_ID * D4 + lane]);
        const float4 r1 = __ldg(&action_table[BOS_ID * D4 + 32 + lane]);
        s_out[(w * 5) * D4 + lane]      = r0;
        s_out[(w * 5) * D4 + 32 + lane] = r1;
    }

    // ---- 4 slot rows per warp; controls via cheap uniform LDS ----
    #pragma unroll
    for (int s = 0; s < SS; ++s) {
        const int lr = w * SS + s;
        const int st = s_st[lr];
        float4 r0, r1;
        if (st == 0) {
            const int len = s_len[lr];                    // 1..15
            const int4* ids4 = (const int4*)(s_ids + lr * LL);
            float4 a0 = make_float4(0.f, 0.f, 0.f, 0.f);
            float4 a1 = make_float4(0.f, 0.f, 0.f, 0.f);
            const int nb = (len + 3) >> 2;                // 1..4
            #pragma unroll 1
            for (int i = 0; i < nb; ++i) {
                const int4 id = ids4[i];                  // LDS.128 uniform
                const int base = i << 2;
                const float4 ex0 = __ldg(&char_table[id.x * D4 + lane]);
                const float4 ex1 = __ldg(&char_table[id.x * D4 + 32 + lane]);
                const float4 ey0 = __ldg(&char_table[id.y * D4 + lane]);
                const float4 ey1 = __ldg(&char_table[id.y * D4 + 32 + lane]);
                const float4 ez0 = __ldg(&char_table[id.z * D4 + lane]);
                const float4 ez1 = __ldg(&char_table[id.z * D4 + 32 + lane]);
                const float4 ew0 = __ldg(&char_table[id.w * D4 + lane]);
                const float4 ew1 = __ldg(&char_table[id.w * D4 + 32 + lane]);
                const float my = (base + 1 < len) ? 1.0f : 0.0f;
                const float mz = (base + 2 < len) ? 1.0f : 0.0f;
                const float mw = (base + 3 < len) ? 1.0f : 0.0f;
                acc4(a0, a1, 1.0f, ex0, ex1);
                acc4(a0, a1, my,   ey0, ey1);
                acc4(a0, a1, mz,   ez0, ez1);
                acc4(a0, a1, mw,   ew0, ew1);
            }
            const float inv = 1.0f / (float)len;
            r0.x = a0.x * inv; r0.y = a0.y * inv; r0.z = a0.z * inv; r0.w = a0.w * inv;
            r1.x = a1.x * inv; r1.y = a1.y * inv; r1.z = a1.z * inv; r1.w = a1.w * inv;
        } else if (st == 1) {
            const int ai = s_ai[lr];
            r0 = __ldg(&action_table[ai * D4 + lane]);
            r1 = __ldg(&action_table[ai * D4 + 32 + lane]);
        } else {
            r0 = make_float4(0.f, 0.f, 0.f, 0.f);
            r1 = make_float4(0.f, 0.f, 0.f, 0.f);
        }
        s_out[(w * 5 + s + 1) * D4 + lane]      = r0;
        s_out[(w * 5 + s + 1) * D4 + 32 + lane] = r1;
    }
    __syncthreads();

    // ---- One bulk S2G copy drains 40 KB: stores leave the LSU path ----
    if (tid == 0) {
        asm volatile("fence.proxy.async.shared::cta;" ::: "memory");
        const unsigned saddr = (unsigned)__cvta_generic_to_shared(s_out);
        float4* gdst = out + (long long)blockIdx.x * OUTR * D4;
        asm volatile(
            "cp.async.bulk.global.shared::cta.bulk_group [%0], [%1], %2;"
            :: "l"(gdst), "r"(saddr), "r"(OUTR * D4 * 16) : "memory");
        asm volatile("cp.async.bulk.commit_group;" ::: "memory");
        asm volatile("cp.async.bulk.wait_group 0;" ::: "memory");
    }
}

extern "C" void kernel_launch(void* const* d_in, const int* in_sizes, int n_in,
                              void* d_out, int out_size)
{
    const int*    char_ids     = (const int*)   d_in[0];
    const int*    char_len     = (const int*)   d_in[1];
    const int*    action_ids   = (const int*)   d_in[2];
    const int*    slot_type    = (const int*)   d_in[3];
    const float4* char_table   = (const float4*)d_in[4];
    const float4* action_table = (const float4*)d_in[5];
    float4*       out          = (float4*)      d_out;

    actions_emb_kernel<<<BLOCKS, THREADS>>>(char_ids, char_len, action_ids,
                                            slot_type, char_table, action_table, out);
}

// round 12
// speedup vs baseline: 1.1764x; 1.1764x over previous
#include <cuda_runtime.h>
#include <cuda_bf16.h>

#define BB 16384
#define SS 4
#define LL 16
#define DD 256
#define BOS_ID 98
#define N_CHAR 58
#define D4 (DD / 4)              // 64 float4 per row
#define OUTROWS (BB * 5)         // 81920

#define THREADS 512
#define BLOCKS  296              // 2 per SM
#define WTOT    (BLOCKS * (THREADS / 32))   // 4736 warps
#define SROWS   48               // table rows resident in smem (48KB)

typedef unsigned long long u64;

__device__ __forceinline__ void add2(u64& a, u64 e) {
    asm("add.rn.f32x2 %0, %0, %1;" : "+l"(a) : "l"(e));
}
__device__ __forceinline__ void fma2(u64& a, u64 m, u64 e) {
    asm("fma.rn.f32x2 %0, %1, %2, %0;" : "+l"(a) : "l"(m), "l"(e));
}
__device__ __forceinline__ u64 dup2(float m) {
    u64 r; asm("mov.b64 %0, {%1, %1};" : "=l"(r) : "f"(m)); return r;
}
__device__ __forceinline__ void mul2(u64& a, u64 m) {
    asm("mul.rn.f32x2 %0, %0, %1;" : "+l"(a) : "l"(m));
}
__device__ __forceinline__ ulonglong2 ld16(const float4* p) {
    return *(const ulonglong2*)p;          // generic 128-bit load (smem or gmem)
}
// Streaming store: evict-first in L2 so dirty output lines drain promptly.
__device__ __forceinline__ void stcs16(ulonglong2* p, ulonglong2 v) {
    asm volatile("st.global.cs.v2.u64 [%0], {%1, %2};"
                 :: "l"(p), "l"(v.x), "l"(v.y) : "memory");
}

__global__ void __launch_bounds__(THREADS, 2) actions_emb_kernel(
    const int*    __restrict__ char_ids,     // (B, S, L)
    const int*    __restrict__ char_len,     // (B, S)
    const int*    __restrict__ action_ids,   // (B, S)
    const int*    __restrict__ slot_type,    // (B, S)
    const float4* __restrict__ char_table,   // (N_CHAR, 64)
    const float4* __restrict__ action_table, // (N_ACT, 64)
    ulonglong2*   __restrict__ out)          // (B, 5, 64)
{
    __shared__ float4 s_tab[SROWS * D4];     // 48 KB

    for (int i = threadIdx.x; i < SROWS * D4; i += THREADS)
        s_tab[i] = __ldg(&char_table[i]);
    __syncthreads();

    const int warp = threadIdx.x >> 5;
    const int lane = threadIdx.x & 31;
    const ulonglong2* at = (const ulonglong2*)action_table;

    for (int row = blockIdx.x * (THREADS / 32) + warp; row < OUTROWS; row += WTOT) {
        const int b = row / 5;
        const int s = row - b * 5;
        ulonglong2 r0, r1;

        if (s == 0) {
            r0 = __ldg(&at[BOS_ID * D4 + lane]);
            r1 = __ldg(&at[BOS_ID * D4 + 32 + lane]);
        } else {
            const int bs = b * SS + s - 1;
            // 7 independent control loads -> one DRAM round-trip.
            const int  st  = __ldg(&slot_type[bs]);
            const int  len = __ldg(&char_len[bs]);        // 1..15
            const int  ai  = __ldg(&action_ids[bs]);
            const int4* p  = (const int4*)(char_ids + bs * LL);
            const int4 i0  = __ldg(&p[0]);
            const int4 i1  = __ldg(&p[1]);
            const int4 i2  = __ldg(&p[2]);
            const int4 i3  = __ldg(&p[3]);

            if (st == 0) {
                u64 a0l = 0, a0h = 0, a1l = 0, a1h = 0;
                #define GPAIR(ia, ib, base)                                        \
                if (len > (base)) {                                                \
                    const float4* pa = ((ia) < SROWS) ? (s_tab + (ia) * D4)        \
                                                      : (char_table + (ia) * D4);  \
                    const float4* pb = ((ib) < SROWS) ? (s_tab + (ib) * D4)        \
                                                      : (char_table + (ib) * D4);  \
                    const ulonglong2 ea0 = ld16(pa + lane);                        \
                    const ulonglong2 ea1 = ld16(pa + 32 + lane);                   \
                    const ulonglong2 eb0 = ld16(pb + lane);                        \
                    const ulonglong2 eb1 = ld16(pb + 32 + lane);                   \
                    add2(a0l, ea0.x); add2(a0h, ea0.y);                            \
                    add2(a1l, ea1.x); add2(a1h, ea1.y);                            \
                    const u64 m = dup2(((base) + 1 < len) ? 1.0f : 0.0f);          \
                    fma2(a0l, m, eb0.x); fma2(a0h, m, eb0.y);                      \
                    fma2(a1l, m, eb1.x); fma2(a1h, m, eb1.y);                      \
                }
                GPAIR(i0.x, i0.y,  0)
                GPAIR(i0.z, i0.w,  2)
                GPAIR(i1.x, i1.y,  4)
                GPAIR(i1.z, i1.w,  6)
                GPAIR(i2.x, i2.y,  8)
                GPAIR(i2.z, i2.w, 10)
                GPAIR(i3.x, i3.y, 12)
                GPAIR(i3.z, i3.w, 14)
                #undef GPAIR
                const u64 inv = dup2(1.0f / (float)len);
                mul2(a0l, inv); mul2(a0h, inv); mul2(a1l, inv); mul2(a1h, inv);
                r0.x = a0l; r0.y = a0h;
                r1.x = a1l; r1.y = a1h;
            } else if (st == 1) {
                r0 = __ldg(&at[ai * D4 + lane]);
                r1 = __ldg(&at[ai * D4 + 32 + lane]);
            } else {
                r0.x = 0; r0.y = 0;
                r1.x = 0; r1.y = 0;
            }
        }

        ulonglong2* o = out + (long long)row * D4;
        stcs16(o + lane,      r0);
        stcs16(o + lane + 32, r1);
    }
}

extern "C" void kernel_launch(void* const* d_in, const int* in_sizes, int n_in,
                              void* d_out, int out_size)
{
    const int*    char_ids     = (const int*)   d_in[0];
    const int*    char_len     = (const int*)   d_in[1];
    const int*    action_ids   = (const int*)   d_in[2];
    const int*    slot_type    = (const int*)   d_in[3];
    const float4* char_table   = (const float4*)d_in[4];
    const float4* action_table = (const float4*)d_in[5];
    ulonglong2*   out          = (ulonglong2*)  d_out;

    actions_emb_kernel<<<BLOCKS, THREADS>>>(char_ids, char_len, action_ids,
                                            slot_type, char_table, action_table, out);
}